// round 1
// baseline (speedup 1.0000x reference)
#include <cuda_runtime.h>
#include <math.h>

typedef unsigned long long ull;

// ---------- f32x2 packed-math helpers (PTX-only path, 2x FFMA throughput) ----------
__device__ __forceinline__ ull pack2(float x, float y){
    ull r; asm("mov.b64 %0, {%1, %2};" : "=l"(r) : "f"(x), "f"(y)); return r;
}
__device__ __forceinline__ void fma2(ull& d, ull a, ull b){
    asm("fma.rn.f32x2 %0, %1, %2, %3;" : "=l"(d) : "l"(a), "l"(b), "l"(d));
}
__device__ __forceinline__ float2 unpack2(ull v){
    float lo, hi; asm("mov.b64 {%0, %1}, %2;" : "=f"(lo), "=f"(hi) : "l"(v));
    return make_float2(lo, hi);
}

#define NN 4096
#define UN 256
#define BT 512

// ---------- static device scratch (no allocations allowed) ----------
__device__ float g_partialG[8u * NN * UN];    // 32 MB: K-split partials of G = adj_mix @ w_gcn
__device__ float g_G[NN * UN];                //  4 MB
__device__ float g_partialX[16u * BT * UN];   //  8 MB: K-split partials of inputs @ G
__device__ float g_X[BT * UN];                //  0.5 MB: relu-reduced X

// =====================================================================
// Kernel A: partialG[ks] = (sum_g wa[g]*adj[g])[m0:m0+128, kchunk] @ w_gcn[kchunk, :]
// BM=128, BN=256, BK=16, 256 threads, grid (32, 8). Graph-mixing fused in A-tile load.
// =====================================================================
#define A_BM 128
#define A_BK 16
#define A_KCHUNK 512

__global__ __launch_bounds__(256, 1) void kernelA(const float* __restrict__ adj,
                                                  const float* __restrict__ wap,
                                                  const float* __restrict__ wgcn)
{
    __shared__ float As[A_BK][A_BM + 4];   // transposed [k][m]
    __shared__ float Bs[A_BK][256];        // [k][n]

    const int tid = threadIdx.x;
    const int tx = tid & 15;               // cols tx*16 .. +15
    const int ty = tid >> 4;               // rows ty*8 .. +7
    const int m0 = blockIdx.x * A_BM;
    const int kbase = blockIdx.y * A_KCHUNK;
    const float w0 = wap[0], w1 = wap[1], w2 = wap[2];
    const size_t GSTRIDE = (size_t)NN * NN;

    // A-tile load coords: float4 id f = tid (+256): row=f/4, c within 16 = (f&3)*4
    const int arow = tid >> 2;
    const int ac4  = (tid & 3) * 4;

    ull acc[8][8];
#pragma unroll
    for (int i = 0; i < 8; i++)
#pragma unroll
        for (int j = 0; j < 8; j++) acc[i][j] = 0ULL;

    float4 pa[2][3], pb[4];
    // prefetch first tile
    {
        const int k0 = kbase;
#pragma unroll
        for (int u = 0; u < 2; u++){
            size_t off = (size_t)(m0 + arow + u*64) * NN + (k0 + ac4);
            pa[u][0] = __ldg((const float4*)(adj + off));
            pa[u][1] = __ldg((const float4*)(adj + GSTRIDE + off));
            pa[u][2] = __ldg((const float4*)(adj + 2*GSTRIDE + off));
        }
#pragma unroll
        for (int j = 0; j < 4; j++){
            int f = tid + j*256; int kk = f >> 6; int n = (f & 63) * 4;
            pb[j] = __ldg((const float4*)(wgcn + (size_t)(k0 + kk) * UN + n));
        }
    }

    const int NITER = A_KCHUNK / A_BK;   // 32
    for (int it = 0; it < NITER; it++){
        // stage prefetched regs -> smem (mix 3 graphs for A)
#pragma unroll
        for (int u = 0; u < 2; u++){
            int row = arow + u*64;
            As[ac4+0][row] = w0*pa[u][0].x + w1*pa[u][1].x + w2*pa[u][2].x;
            As[ac4+1][row] = w0*pa[u][0].y + w1*pa[u][1].y + w2*pa[u][2].y;
            As[ac4+2][row] = w0*pa[u][0].z + w1*pa[u][1].z + w2*pa[u][2].z;
            As[ac4+3][row] = w0*pa[u][0].w + w1*pa[u][1].w + w2*pa[u][2].w;
        }
#pragma unroll
        for (int j = 0; j < 4; j++){
            int f = tid + j*256; int kk = f >> 6; int n = (f & 63) * 4;
            *(float4*)&Bs[kk][n] = pb[j];
        }
        __syncthreads();

        // prefetch next tile while computing this one
        if (it + 1 < NITER){
            const int k0 = kbase + (it + 1) * A_BK;
#pragma unroll
            for (int u = 0; u < 2; u++){
                size_t off = (size_t)(m0 + arow + u*64) * NN + (k0 + ac4);
                pa[u][0] = __ldg((const float4*)(adj + off));
                pa[u][1] = __ldg((const float4*)(adj + GSTRIDE + off));
                pa[u][2] = __ldg((const float4*)(adj + 2*GSTRIDE + off));
            }
#pragma unroll
            for (int j = 0; j < 4; j++){
                int f = tid + j*256; int kk = f >> 6; int n = (f & 63) * 4;
                pb[j] = __ldg((const float4*)(wgcn + (size_t)(k0 + kk) * UN + n));
            }
        }

#pragma unroll 4
        for (int kk = 0; kk < A_BK; kk++){
            const float4* ar = (const float4*)&As[kk][ty*8];
            float4 a0 = ar[0], a1 = ar[1];
            float av[8] = {a0.x,a0.y,a0.z,a0.w,a1.x,a1.y,a1.z,a1.w};
            const ulonglong2* bp = (const ulonglong2*)&Bs[kk][tx*16];
            ulonglong2 t0 = bp[0], t1 = bp[1], t2 = bp[2], t3 = bp[3];
            ull bv[8] = {t0.x,t0.y,t1.x,t1.y,t2.x,t2.y,t3.x,t3.y};
#pragma unroll
            for (int i = 0; i < 8; i++){
                ull aa = pack2(av[i], av[i]);
#pragma unroll
                for (int j = 0; j < 8; j++) fma2(acc[i][j], aa, bv[j]);
            }
        }
        __syncthreads();
    }

    // epilogue: contiguous 64B per (thread,row)
    float* dst = g_partialG + (size_t)blockIdx.y * (NN * UN);
#pragma unroll
    for (int i = 0; i < 8; i++){
        int row = m0 + ty*8 + i;
        ulonglong2* dp = (ulonglong2*)(dst + (size_t)row * UN + tx*16);
        dp[0] = make_ulonglong2(acc[i][0], acc[i][1]);
        dp[1] = make_ulonglong2(acc[i][2], acc[i][3]);
        dp[2] = make_ulonglong2(acc[i][4], acc[i][5]);
        dp[3] = make_ulonglong2(acc[i][6], acc[i][7]);
    }
}

// =====================================================================
// Reduce G = sum of 8 partials
// =====================================================================
__global__ void kReduceG()
{
    int i = blockIdx.x * blockDim.x + threadIdx.x;   // 262144 float4s
    const float4* p = (const float4*)g_partialG;
    float4 s = p[i];
#pragma unroll
    for (int s8 = 1; s8 < 8; s8++){
        float4 t = p[(size_t)s8 * (NN*UN/4) + i];
        s.x += t.x; s.y += t.y; s.z += t.z; s.w += t.w;
    }
    ((float4*)g_G)[i] = s;
}

// =====================================================================
// Kernel B: partialX[ks] = inputs[m0:m0+64, kchunk] @ G[kchunk, :]
// BM=64, BN=256, BK=16, 256 threads, grid (8, 16)
// =====================================================================
#define B_BM 64
#define B_BK 16
#define B_KCHUNK 256

__global__ __launch_bounds__(256, 2) void kernelB(const float* __restrict__ inputs)
{
    __shared__ float As[B_BK][B_BM + 4];
    __shared__ float Bs[B_BK][256];

    const int tid = threadIdx.x;
    const int tx = tid & 15;     // cols tx*16
    const int ty = tid >> 4;     // rows ty*4
    const int m0 = blockIdx.x * B_BM;
    const int kbase = blockIdx.y * B_KCHUNK;

    const int arow = tid >> 2;           // 0..63
    const int ac4  = (tid & 3) * 4;

    ull acc[4][8];
#pragma unroll
    for (int i = 0; i < 4; i++)
#pragma unroll
        for (int j = 0; j < 8; j++) acc[i][j] = 0ULL;

    float4 pa, pb[4];
    {
        const int k0 = kbase;
        pa = __ldg((const float4*)(inputs + (size_t)(m0 + arow) * NN + k0 + ac4));
#pragma unroll
        for (int j = 0; j < 4; j++){
            int f = tid + j*256; int kk = f >> 6; int n = (f & 63) * 4;
            pb[j] = *(const float4*)(g_G + (size_t)(k0 + kk) * UN + n);
        }
    }

    const int NITER = B_KCHUNK / B_BK;  // 16
    for (int it = 0; it < NITER; it++){
        As[ac4+0][arow] = pa.x; As[ac4+1][arow] = pa.y;
        As[ac4+2][arow] = pa.z; As[ac4+3][arow] = pa.w;
#pragma unroll
        for (int j = 0; j < 4; j++){
            int f = tid + j*256; int kk = f >> 6; int n = (f & 63) * 4;
            *(float4*)&Bs[kk][n] = pb[j];
        }
        __syncthreads();

        if (it + 1 < NITER){
            const int k0 = kbase + (it + 1) * B_BK;
            pa = __ldg((const float4*)(inputs + (size_t)(m0 + arow) * NN + k0 + ac4));
#pragma unroll
            for (int j = 0; j < 4; j++){
                int f = tid + j*256; int kk = f >> 6; int n = (f & 63) * 4;
                pb[j] = *(const float4*)(g_G + (size_t)(k0 + kk) * UN + n);
            }
        }

#pragma unroll 4
        for (int kk = 0; kk < B_BK; kk++){
            const float4* ar = (const float4*)&As[kk][ty*4];
            float4 a0 = ar[0];
            float av[4] = {a0.x,a0.y,a0.z,a0.w};
            const ulonglong2* bp = (const ulonglong2*)&Bs[kk][tx*16];
            ulonglong2 t0 = bp[0], t1 = bp[1], t2 = bp[2], t3 = bp[3];
            ull bv[8] = {t0.x,t0.y,t1.x,t1.y,t2.x,t2.y,t3.x,t3.y};
#pragma unroll
            for (int i = 0; i < 4; i++){
                ull aa = pack2(av[i], av[i]);
#pragma unroll
                for (int j = 0; j < 8; j++) fma2(acc[i][j], aa, bv[j]);
            }
        }
        __syncthreads();
    }

    float* dst = g_partialX + (size_t)blockIdx.y * (BT * UN);
#pragma unroll
    for (int i = 0; i < 4; i++){
        int row = m0 + ty*4 + i;
        ulonglong2* dp = (ulonglong2*)(dst + (size_t)row * UN + tx*16);
        dp[0] = make_ulonglong2(acc[i][0], acc[i][1]);
        dp[1] = make_ulonglong2(acc[i][2], acc[i][3]);
        dp[2] = make_ulonglong2(acc[i][4], acc[i][5]);
        dp[3] = make_ulonglong2(acc[i][6], acc[i][7]);
    }
}

// =====================================================================
// Reduce + ReLU: X = relu(sum of 16 partials)
// =====================================================================
__global__ void kReduceX()
{
    int i = blockIdx.x * blockDim.x + threadIdx.x;   // 32768 float4s
    const float4* p = (const float4*)g_partialX;
    float4 s = p[i];
#pragma unroll
    for (int s16 = 1; s16 < 16; s16++){
        float4 t = p[(size_t)s16 * (BT*UN/4) + i];
        s.x += t.x; s.y += t.y; s.z += t.z; s.w += t.w;
    }
    s.x = fmaxf(s.x, 0.f); s.y = fmaxf(s.y, 0.f);
    s.z = fmaxf(s.z, 0.f); s.w = fmaxf(s.w, 0.f);
    ((float4*)g_X)[i] = s;
}

// =====================================================================
// Kernel C: GRU gates. out = (1-z)*state + z*h
// z = sigmoid(X@wz + state@uz + bz), h = tanh(X@wh + state@uh + bh)
// BM=32, BN=32, BK=32, 128 threads, grid (16, 8)
// =====================================================================
__global__ __launch_bounds__(128, 4) void kernelC(const float* __restrict__ state,
    const float* __restrict__ wz, const float* __restrict__ uz, const float* __restrict__ bz,
    const float* __restrict__ wh, const float* __restrict__ uh, const float* __restrict__ bh,
    float* __restrict__ out)
{
    __shared__ float Xs[32][33];   // transposed [k][row]
    __shared__ float Ss[32][33];
    __shared__ float Wz[32][32], Uz[32][32], Wh[32][32], Uh[32][32];

    const int tid = threadIdx.x;
    const int tx = tid & 7;        // cols tx*4
    const int ty = tid >> 3;       // rows ty*2
    const int m0 = blockIdx.x * 32;
    const int n0 = blockIdx.y * 32;

    ull accz[2][2], acch[2][2];
#pragma unroll
    for (int i = 0; i < 2; i++)
#pragma unroll
        for (int j = 0; j < 2; j++){ accz[i][j] = 0ULL; acch[i][j] = 0ULL; }

    for (int kt = 0; kt < UN / 32; kt++){
        const int k0 = kt * 32;
        // loads first (latency overlaps other warps' compute), then stage
        float4 xv[2], sv[2], wzv[2], uzv[2], whv[2], uhv[2];
#pragma unroll
        for (int u = 0; u < 2; u++){
            int f = tid + 128*u;
            int row = f >> 3; int c4 = (f & 7) * 4;
            xv[u]  = *(const float4*)(g_X  + (size_t)(m0 + row) * UN + k0 + c4);
            sv[u]  = *(const float4*)(state + (size_t)(m0 + row) * UN + k0 + c4);
            wzv[u] = *(const float4*)(wz + (size_t)(k0 + row) * UN + n0 + c4);
            uzv[u] = *(const float4*)(uz + (size_t)(k0 + row) * UN + n0 + c4);
            whv[u] = *(const float4*)(wh + (size_t)(k0 + row) * UN + n0 + c4);
            uhv[u] = *(const float4*)(uh + (size_t)(k0 + row) * UN + n0 + c4);
        }
        __syncthreads();
#pragma unroll
        for (int u = 0; u < 2; u++){
            int f = tid + 128*u;
            int row = f >> 3; int c4 = (f & 7) * 4;
            Xs[c4+0][row] = xv[u].x; Xs[c4+1][row] = xv[u].y;
            Xs[c4+2][row] = xv[u].z; Xs[c4+3][row] = xv[u].w;
            Ss[c4+0][row] = sv[u].x; Ss[c4+1][row] = sv[u].y;
            Ss[c4+2][row] = sv[u].z; Ss[c4+3][row] = sv[u].w;
            *(float4*)&Wz[row][c4] = wzv[u];
            *(float4*)&Uz[row][c4] = uzv[u];
            *(float4*)&Wh[row][c4] = whv[u];
            *(float4*)&Uh[row][c4] = uhv[u];
        }
        __syncthreads();

#pragma unroll 8
        for (int kk = 0; kk < 32; kk++){
            float x0 = Xs[kk][ty*2], x1 = Xs[kk][ty*2+1];
            float s0 = Ss[kk][ty*2], s1 = Ss[kk][ty*2+1];
            ull xx0 = pack2(x0, x0), xx1 = pack2(x1, x1);
            ull ss0 = pack2(s0, s0), ss1 = pack2(s1, s1);
            const ull* wzp = (const ull*)&Wz[kk][tx*4];
            const ull* uzp = (const ull*)&Uz[kk][tx*4];
            const ull* whp = (const ull*)&Wh[kk][tx*4];
            const ull* uhp = (const ull*)&Uh[kk][tx*4];
            ull wz0 = wzp[0], wz1 = wzp[1], uz0 = uzp[0], uz1 = uzp[1];
            ull wh0 = whp[0], wh1 = whp[1], uh0 = uhp[0], uh1 = uhp[1];
            fma2(accz[0][0], xx0, wz0); fma2(accz[0][1], xx0, wz1);
            fma2(accz[1][0], xx1, wz0); fma2(accz[1][1], xx1, wz1);
            fma2(accz[0][0], ss0, uz0); fma2(accz[0][1], ss0, uz1);
            fma2(accz[1][0], ss1, uz0); fma2(accz[1][1], ss1, uz1);
            fma2(acch[0][0], xx0, wh0); fma2(acch[0][1], xx0, wh1);
            fma2(acch[1][0], xx1, wh0); fma2(acch[1][1], xx1, wh1);
            fma2(acch[0][0], ss0, uh0); fma2(acch[0][1], ss0, uh1);
            fma2(acch[1][0], ss1, uh0); fma2(acch[1][1], ss1, uh1);
        }
    }

#pragma unroll
    for (int i = 0; i < 2; i++){
        int row = m0 + ty*2 + i;
#pragma unroll
        for (int jp = 0; jp < 2; jp++){
            float2 vz = unpack2(accz[i][jp]);
            float2 vh = unpack2(acch[i][jp]);
            int c = n0 + tx*4 + jp*2;
#pragma unroll
            for (int w = 0; w < 2; w++){
                float pz = (w ? vz.y : vz.x) + bz[c + w];
                float ph = (w ? vh.y : vh.x) + bh[c + w];
                float z = 1.0f / (1.0f + expf(-pz));
                float h = tanhf(ph);
                float st = state[(size_t)row * UN + c + w];
                out[(size_t)row * UN + c + w] = st + z * (h - st);
            }
        }
    }
}

// =====================================================================
extern "C" void kernel_launch(void* const* d_in, const int* in_sizes, int n_in,
                              void* d_out, int out_size)
{
    const float* inputs = (const float*)d_in[0];
    const float* state  = (const float*)d_in[1];
    const float* adj    = (const float*)d_in[2];
    const float* wa     = (const float*)d_in[3];
    const float* wgcn   = (const float*)d_in[4];
    const float* wz     = (const float*)d_in[5];
    const float* uz     = (const float*)d_in[6];
    const float* bz     = (const float*)d_in[7];
    const float* wh     = (const float*)d_in[8];
    const float* uh     = (const float*)d_in[9];
    const float* bh     = (const float*)d_in[10];
    float* out = (float*)d_out;

    kernelA<<<dim3(32, 8), 256>>>(adj, wa, wgcn);
    kReduceG<<<1024, 256>>>();
    kernelB<<<dim3(8, 16), 256>>>(inputs);
    kReduceX<<<128, 256>>>();
    kernelC<<<dim3(16, 8), 128>>>(state, wz, uz, bz, wh, uh, bh, out);
}

// round 3
// speedup vs baseline: 2.8874x; 2.8874x over previous
#include <cuda_runtime.h>
#include <math.h>
#include <stdint.h>

typedef unsigned long long ull;
typedef unsigned short u16;

#define NN 4096
#define UN 256
#define BT 512

// ================= helpers =================
__device__ __forceinline__ ull pack2(float x, float y){
    ull r; asm("mov.b64 %0, {%1, %2};" : "=l"(r) : "f"(x), "f"(y)); return r;
}
__device__ __forceinline__ void fma2(ull& d, ull a, ull b){
    asm("fma.rn.f32x2 %0, %1, %2, %3;" : "=l"(d) : "l"(a), "l"(b), "l"(d));
}
__device__ __forceinline__ float2 unpack2(ull v){
    float lo, hi; asm("mov.b64 {%0, %1}, %2;" : "=f"(lo), "=f"(hi) : "l"(v));
    return make_float2(lo, hi);
}
__device__ __forceinline__ uint32_t smem_u32(const void* p){
    uint32_t a;
    asm("{ .reg .u64 t; cvta.to.shared.u64 t, %1; cvt.u32.u64 %0, t; }" : "=r"(a) : "l"(p));
    return a;
}
__device__ __forceinline__ void cpasync16(uint32_t daddr, const void* gptr){
    asm volatile("cp.async.cg.shared.global [%0], [%1], 16;" :: "r"(daddr), "l"(gptr));
}
#define CP_COMMIT asm volatile("cp.async.commit_group;" ::: "memory")
#define CP_WAIT0  asm volatile("cp.async.wait_group 0;" ::: "memory")

// bf16 hi/lo split of a pair of floats -> packed bf16x2 words (low k in low 16 bits)
__device__ __forceinline__ void split2(float v0, float v1, uint32_t& hp, uint32_t& lp){
    u16 h0, h1, l0, l1;
    asm("cvt.rn.bf16.f32 %0, %1;" : "=h"(h0) : "f"(v0));
    asm("cvt.rn.bf16.f32 %0, %1;" : "=h"(h1) : "f"(v1));
    float f0 = __uint_as_float((uint32_t)h0 << 16);
    float f1 = __uint_as_float((uint32_t)h1 << 16);
    asm("cvt.rn.bf16.f32 %0, %1;" : "=h"(l0) : "f"(v0 - f0));
    asm("cvt.rn.bf16.f32 %0, %1;" : "=h"(l1) : "f"(v1 - f1));
    asm("mov.b32 %0, {%1, %2};" : "=r"(hp) : "h"(h0), "h"(h1));
    asm("mov.b32 %0, {%1, %2};" : "=r"(lp) : "h"(l0), "h"(l1));
}
__device__ __forceinline__ void split1(float v, u16& h, u16& l){
    u16 hb, lb;
    asm("cvt.rn.bf16.f32 %0, %1;" : "=h"(hb) : "f"(v));
    float hf = __uint_as_float((uint32_t)hb << 16);
    asm("cvt.rn.bf16.f32 %0, %1;" : "=h"(lb) : "f"(v - hf));
    h = hb; l = lb;
}

__device__ __forceinline__ void mma16816(float* d, const uint32_t* a, const uint32_t* b){
    asm volatile("mma.sync.aligned.m16n8k16.row.col.f32.bf16.bf16.f32 "
        "{%0,%1,%2,%3}, {%4,%5,%6,%7}, {%8,%9}, {%0,%1,%2,%3};"
        : "+f"(d[0]), "+f"(d[1]), "+f"(d[2]), "+f"(d[3])
        : "r"(a[0]), "r"(a[1]), "r"(a[2]), "r"(a[3]), "r"(b[0]), "r"(b[1]));
}

// ================= static device scratch =================
__device__ __align__(16) float g_partialG[2u * NN * UN];   // 8 MB
__device__ __align__(16) u16   g_wtb_hi[UN * NN];          // 2 MB  w_gcn^T bf16 hi [256][4096]
__device__ __align__(16) u16   g_wtb_lo[UN * NN];          // 2 MB
__device__ __align__(16) u16   g_Gt_hi[UN * NN];           // 2 MB  G^T bf16 hi [256][4096]
__device__ __align__(16) u16   g_Gt_lo[UN * NN];           // 2 MB
__device__ __align__(16) u16   g_inb_hi[BT * NN];          // 4 MB  inputs bf16 hi [512][4096]
__device__ __align__(16) u16   g_inb_lo[BT * NN];          // 4 MB
__device__ __align__(16) float g_partialX[16u * BT * UN];  // 8 MB
__device__ __align__(16) float g_X[BT * UN];               // 0.5 MB

// ================= SMEM tile geometry (shared by kernelA/B) =================
// tiles: A 128 rows x 32 k (bf16 hi/lo), B 128 n-rows x 32 k (bf16 hi/lo)
// row stride 80 bytes (40 halves): conflict-free for frag LDS, 16B-aligned
#define ROWB 80
#define OFF_AHI 0
#define OFF_ALO 10240
#define OFF_BHI 20480
#define OFF_BLO 30720
#define BUFST   40960
#define SMEMSZ  (2 * BUFST)

// one double-K16 mma stage over a filled buffer (BK=32)
__device__ __forceinline__ void mma_stage(const char* buf, float (&acc)[4][4][4],
                                          int wid, int g, int tig){
    const int am = (wid & 1) * 64 + g;       // + mi*16
    const int bn = (wid >> 1) * 32 + g;      // + ni*8
#pragma unroll
    for (int s = 0; s < 2; s++){
        const int ko = s * 32 + tig * 4;
        uint32_t bh[4][2], bl[4][2];
#pragma unroll
        for (int ni = 0; ni < 4; ni++){
            const char* p = buf + OFF_BHI + (bn + ni*8) * ROWB + ko;
            bh[ni][0] = *(const uint32_t*)p;
            bh[ni][1] = *(const uint32_t*)(p + 16);
            const char* q = buf + OFF_BLO + (bn + ni*8) * ROWB + ko;
            bl[ni][0] = *(const uint32_t*)q;
            bl[ni][1] = *(const uint32_t*)(q + 16);
        }
#pragma unroll
        for (int mi = 0; mi < 4; mi++){
            const char* p = buf + OFF_AHI + (am + mi*16) * ROWB + ko;
            uint32_t ah[4] = { *(const uint32_t*)p,        *(const uint32_t*)(p + 8*ROWB),
                               *(const uint32_t*)(p + 16), *(const uint32_t*)(p + 8*ROWB + 16) };
            const char* q = buf + OFF_ALO + (am + mi*16) * ROWB + ko;
            uint32_t al[4] = { *(const uint32_t*)q,        *(const uint32_t*)(q + 8*ROWB),
                               *(const uint32_t*)(q + 16), *(const uint32_t*)(q + 8*ROWB + 16) };
#pragma unroll
            for (int ni = 0; ni < 4; ni++){
                mma16816(acc[mi][ni], ah, bh[ni]);
                mma16816(acc[mi][ni], ah, bl[ni]);
                mma16816(acc[mi][ni], al, bh[ni]);
            }
        }
    }
}

// =====================================================================
// kPrepW: w_gcn [4096][256] -> g_wtb_hi/lo [256][4096] (transpose + split)
// =====================================================================
__global__ void kPrepW(const float* __restrict__ wgcn)
{
    __shared__ float tile[32][33];
    const int k0 = blockIdx.x * 32, n0 = blockIdx.y * 32;
    const int c = threadIdx.x & 31, r = threadIdx.x >> 5;  // r 0..7
#pragma unroll
    for (int i = 0; i < 4; i++)
        tile[r + 8*i][c] = wgcn[(size_t)(k0 + r + 8*i) * UN + n0 + c];
    __syncthreads();
#pragma unroll
    for (int i = 0; i < 4; i++){
        float v = tile[c][r + 8*i];
        size_t o = (size_t)(n0 + r + 8*i) * NN + k0 + c;
        split1(v, g_wtb_hi[o], g_wtb_lo[o]);
    }
}

// =====================================================================
// kPrepIn: inputs [512][4096] fp32 -> g_inb_hi/lo bf16
// =====================================================================
__global__ void kPrepIn(const float* __restrict__ inputs)
{
    int i = blockIdx.x * blockDim.x + threadIdx.x;    // 524288 float4s
    float4 v = ((const float4*)inputs)[i];
    uint32_t h0, l0, h1, l1;
    split2(v.x, v.y, h0, l0);
    split2(v.z, v.w, h1, l1);
    ((uint2*)g_inb_hi)[i] = make_uint2(h0, h1);
    ((uint2*)g_inb_lo)[i] = make_uint2(l0, l1);
}

// =====================================================================
// kernelA: partialG[ks] = adj_mix[:, ks*2048:+2048] @ w_gcn  via mma.sync bf16 x3
// grid (32 m-tiles, 2 n-tiles, 2 ksplit), 256 threads
// =====================================================================
#define KA_NST 64     // 2048 / 32

__global__ __launch_bounds__(256, 1) void kernelA(const float* __restrict__ adj,
                                                  const float* __restrict__ wap)
{
    extern __shared__ __align__(16) char smem[];
    const uint32_t sb = smem_u32(smem);
    const int tid = threadIdx.x, wid = tid >> 5, lane = tid & 31;
    const int g = lane >> 2, tig = lane & 3;
    const int m0 = blockIdx.x * 128, n0 = blockIdx.y * 128;
    const int kbase = blockIdx.z * 2048;
    const float w0 = wap[0], w1 = wap[1], w2 = wap[2];
    const size_t GS = (size_t)NN * NN;

    float acc[4][4][4];
#pragma unroll
    for (int a = 0; a < 4; a++)
#pragma unroll
        for (int b = 0; b < 4; b++)
#pragma unroll
            for (int c = 0; c < 4; c++) acc[a][b][c] = 0.f;

    float4 ra[4][3];

    auto issueB = [&](int t, int b){
#pragma unroll
        for (int j = 0; j < 2; j++){
            int f = j*256 + tid, row = f >> 2, c = f & 3;
            uint32_t daddr = sb + b*BUFST + row*ROWB + c*16;
            size_t go = (size_t)(n0 + row) * NN + kbase + t*32 + c*8;
            cpasync16(daddr + OFF_BHI, g_wtb_hi + go);
            cpasync16(daddr + OFF_BLO, g_wtb_lo + go);
        }
        CP_COMMIT;
    };
    auto loadA = [&](int t){
#pragma unroll
        for (int j = 0; j < 4; j++){
            int f = j*256 + tid, row = f >> 3, q = f & 7;
            const float* p = adj + (size_t)(m0 + row) * NN + kbase + t*32 + q*4;
            ra[j][0] = __ldg((const float4*)p);
            ra[j][1] = __ldg((const float4*)(p + GS));
            ra[j][2] = __ldg((const float4*)(p + 2*GS));
        }
    };
    auto storeA = [&](int b){
        char* base = smem + b*BUFST;
#pragma unroll
        for (int j = 0; j < 4; j++){
            int f = j*256 + tid, row = f >> 3, q = f & 7;
            float vx = fmaf(w0, ra[j][0].x, fmaf(w1, ra[j][1].x, w2*ra[j][2].x));
            float vy = fmaf(w0, ra[j][0].y, fmaf(w1, ra[j][1].y, w2*ra[j][2].y));
            float vz = fmaf(w0, ra[j][0].z, fmaf(w1, ra[j][1].z, w2*ra[j][2].z));
            float vw = fmaf(w0, ra[j][0].w, fmaf(w1, ra[j][1].w, w2*ra[j][2].w));
            uint32_t h0, l0, h1, l1;
            split2(vx, vy, h0, l0);
            split2(vz, vw, h1, l1);
            *(uint2*)(base + OFF_AHI + row*ROWB + q*8) = make_uint2(h0, h1);
            *(uint2*)(base + OFF_ALO + row*ROWB + q*8) = make_uint2(l0, l1);
        }
    };

    // prologue
    issueB(0, 0);
    loadA(0); storeA(0);
    CP_WAIT0; __syncthreads();

    for (int t = 0; t < KA_NST; t++){
        const int b = t & 1;
        if (t + 1 < KA_NST){ issueB(t + 1, b ^ 1); loadA(t + 1); }
        mma_stage(smem + b*BUFST, acc, wid, g, tig);
        if (t + 1 < KA_NST) storeA(b ^ 1);
        CP_WAIT0; __syncthreads();
    }

    // epilogue
    float* dst = g_partialG + (size_t)blockIdx.z * (NN * UN);
#pragma unroll
    for (int mi = 0; mi < 4; mi++){
#pragma unroll
        for (int ni = 0; ni < 4; ni++){
            int m = m0 + (wid & 1)*64 + mi*16 + g;
            int n = n0 + (wid >> 1)*32 + ni*8 + tig*2;
            *(float2*)(dst + (size_t)m * UN + n)       = make_float2(acc[mi][ni][0], acc[mi][ni][1]);
            *(float2*)(dst + (size_t)(m + 8) * UN + n) = make_float2(acc[mi][ni][2], acc[mi][ni][3]);
        }
    }
}

// =====================================================================
// kReduceGT: G = sum of 2 partials; transpose + bf16 split -> g_Gt_hi/lo [256][4096]
// =====================================================================
__global__ void kReduceGT()
{
    __shared__ float tile[32][33];
    const int k0 = blockIdx.x * 32, n0 = blockIdx.y * 32;
    const int c = threadIdx.x & 31, r = threadIdx.x >> 5;
#pragma unroll
    for (int i = 0; i < 4; i++){
        size_t o = (size_t)(k0 + r + 8*i) * UN + n0 + c;
        tile[r + 8*i][c] = g_partialG[o] + g_partialG[(size_t)NN*UN + o];
    }
    __syncthreads();
#pragma unroll
    for (int i = 0; i < 4; i++){
        float v = tile[c][r + 8*i];
        size_t o = (size_t)(n0 + r + 8*i) * NN + k0 + c;
        split1(v, g_Gt_hi[o], g_Gt_lo[o]);
    }
}

// =====================================================================
// kernelB: partialX[ks] = inputs[:, kchunk] @ G[kchunk, :]  via mma.sync bf16 x3
// grid (4 m-tiles, 2 n-tiles, 16 ksplit), kchunk 256, NST 8
// =====================================================================
#define KB_NST 8

__global__ __launch_bounds__(256, 1) void kernelB()
{
    extern __shared__ __align__(16) char smem[];
    const uint32_t sb = smem_u32(smem);
    const int tid = threadIdx.x, wid = tid >> 5, lane = tid & 31;
    const int g = lane >> 2, tig = lane & 3;
    const int m0 = blockIdx.x * 128, n0 = blockIdx.y * 128;
    const int kbase = blockIdx.z * 256;

    float acc[4][4][4];
#pragma unroll
    for (int a = 0; a < 4; a++)
#pragma unroll
        for (int b = 0; b < 4; b++)
#pragma unroll
            for (int c = 0; c < 4; c++) acc[a][b][c] = 0.f;

    auto issue = [&](int t, int b){
#pragma unroll
        for (int j = 0; j < 2; j++){
            int f = j*256 + tid, row = f >> 2, c = f & 3;
            uint32_t daddr = sb + b*BUFST + row*ROWB + c*16;
            size_t ga = (size_t)(m0 + row) * NN + kbase + t*32 + c*8;
            size_t gb = (size_t)(n0 + row) * NN + kbase + t*32 + c*8;
            cpasync16(daddr + OFF_AHI, g_inb_hi + ga);
            cpasync16(daddr + OFF_ALO, g_inb_lo + ga);
            cpasync16(daddr + OFF_BHI, g_Gt_hi + gb);
            cpasync16(daddr + OFF_BLO, g_Gt_lo + gb);
        }
        CP_COMMIT;
    };

    issue(0, 0);
    CP_WAIT0; __syncthreads();

    for (int t = 0; t < KB_NST; t++){
        const int b = t & 1;
        if (t + 1 < KB_NST) issue(t + 1, b ^ 1);
        mma_stage(smem + b*BUFST, acc, wid, g, tig);
        CP_WAIT0; __syncthreads();
    }

    float* dst = g_partialX + (size_t)blockIdx.z * (BT * UN);
#pragma unroll
    for (int mi = 0; mi < 4; mi++){
#pragma unroll
        for (int ni = 0; ni < 4; ni++){
            int m = m0 + (wid & 1)*64 + mi*16 + g;
            int n = n0 + (wid >> 1)*32 + ni*8 + tig*2;
            *(float2*)(dst + (size_t)m * UN + n)       = make_float2(acc[mi][ni][0], acc[mi][ni][1]);
            *(float2*)(dst + (size_t)(m + 8) * UN + n) = make_float2(acc[mi][ni][2], acc[mi][ni][3]);
        }
    }
}

// =====================================================================
// kReduceX: X = relu(sum of 16 partials)
// =====================================================================
__global__ void kReduceX()
{
    int i = blockIdx.x * blockDim.x + threadIdx.x;   // 32768 float4s
    const float4* p = (const float4*)g_partialX;
    float4 s = p[i];
#pragma unroll
    for (int s16 = 1; s16 < 16; s16++){
        float4 t = p[(size_t)s16 * (BT*UN/4) + i];
        s.x += t.x; s.y += t.y; s.z += t.z; s.w += t.w;
    }
    s.x = fmaxf(s.x, 0.f); s.y = fmaxf(s.y, 0.f);
    s.z = fmaxf(s.z, 0.f); s.w = fmaxf(s.w, 0.f);
    ((float4*)g_X)[i] = s;
}

// =====================================================================
// kernelC: GRU gates (fp32 CUDA cores, unchanged from R1)
// =====================================================================
__global__ __launch_bounds__(128, 4) void kernelC(const float* __restrict__ state,
    const float* __restrict__ wz, const float* __restrict__ uz, const float* __restrict__ bz,
    const float* __restrict__ wh, const float* __restrict__ uh, const float* __restrict__ bh,
    float* __restrict__ out)
{
    __shared__ float Xs[32][33];
    __shared__ float Ss[32][33];
    __shared__ float Wz[32][32], Uz[32][32], Wh[32][32], Uh[32][32];

    const int tid = threadIdx.x;
    const int tx = tid & 7;
    const int ty = tid >> 3;
    const int m0 = blockIdx.x * 32;
    const int n0 = blockIdx.y * 32;

    ull accz[2][2], acch[2][2];
#pragma unroll
    for (int i = 0; i < 2; i++)
#pragma unroll
        for (int j = 0; j < 2; j++){ accz[i][j] = 0ULL; acch[i][j] = 0ULL; }

    for (int kt = 0; kt < UN / 32; kt++){
        const int k0 = kt * 32;
        float4 xv[2], sv[2], wzv[2], uzv[2], whv[2], uhv[2];
#pragma unroll
        for (int u = 0; u < 2; u++){
            int f = tid + 128*u;
            int row = f >> 3; int c4 = (f & 7) * 4;
            xv[u]  = *(const float4*)(g_X  + (size_t)(m0 + row) * UN + k0 + c4);
            sv[u]  = *(const float4*)(state + (size_t)(m0 + row) * UN + k0 + c4);
            wzv[u] = *(const float4*)(wz + (size_t)(k0 + row) * UN + n0 + c4);
            uzv[u] = *(const float4*)(uz + (size_t)(k0 + row) * UN + n0 + c4);
            whv[u] = *(const float4*)(wh + (size_t)(k0 + row) * UN + n0 + c4);
            uhv[u] = *(const float4*)(uh + (size_t)(k0 + row) * UN + n0 + c4);
        }
        __syncthreads();
#pragma unroll
        for (int u = 0; u < 2; u++){
            int f = tid + 128*u;
            int row = f >> 3; int c4 = (f & 7) * 4;
            Xs[c4+0][row] = xv[u].x; Xs[c4+1][row] = xv[u].y;
            Xs[c4+2][row] = xv[u].z; Xs[c4+3][row] = xv[u].w;
            Ss[c4+0][row] = sv[u].x; Ss[c4+1][row] = sv[u].y;
            Ss[c4+2][row] = sv[u].z; Ss[c4+3][row] = sv[u].w;
            *(float4*)&Wz[row][c4] = wzv[u];
            *(float4*)&Uz[row][c4] = uzv[u];
            *(float4*)&Wh[row][c4] = whv[u];
            *(float4*)&Uh[row][c4] = uhv[u];
        }
        __syncthreads();

#pragma unroll 8
        for (int kk = 0; kk < 32; kk++){
            float x0 = Xs[kk][ty*2], x1 = Xs[kk][ty*2+1];
            float s0 = Ss[kk][ty*2], s1 = Ss[kk][ty*2+1];
            ull xx0 = pack2(x0, x0), xx1 = pack2(x1, x1);
            ull ss0 = pack2(s0, s0), ss1 = pack2(s1, s1);
            const ull* wzp = (const ull*)&Wz[kk][tx*4];
            const ull* uzp = (const ull*)&Uz[kk][tx*4];
            const ull* whp = (const ull*)&Wh[kk][tx*4];
            const ull* uhp = (const ull*)&Uh[kk][tx*4];
            ull wz0 = wzp[0], wz1 = wzp[1], uz0 = uzp[0], uz1 = uzp[1];
            ull wh0 = whp[0], wh1 = whp[1], uh0 = uhp[0], uh1 = uhp[1];
            fma2(accz[0][0], xx0, wz0); fma2(accz[0][1], xx0, wz1);
            fma2(accz[1][0], xx1, wz0); fma2(accz[1][1], xx1, wz1);
            fma2(accz[0][0], ss0, uz0); fma2(accz[0][1], ss0, uz1);
            fma2(accz[1][0], ss1, uz0); fma2(accz[1][1], ss1, uz1);
            fma2(acch[0][0], xx0, wh0); fma2(acch[0][1], xx0, wh1);
            fma2(acch[1][0], xx1, wh0); fma2(acch[1][1], xx1, wh1);
            fma2(acch[0][0], ss0, uh0); fma2(acch[0][1], ss0, uh1);
            fma2(acch[1][0], ss1, uh0); fma2(acch[1][1], ss1, uh1);
        }
    }

#pragma unroll
    for (int i = 0; i < 2; i++){
        int row = m0 + ty*2 + i;
#pragma unroll
        for (int jp = 0; jp < 2; jp++){
            float2 vz = unpack2(accz[i][jp]);
            float2 vh = unpack2(acch[i][jp]);
            int c = n0 + tx*4 + jp*2;
#pragma unroll
            for (int w = 0; w < 2; w++){
                float pz = (w ? vz.y : vz.x) + bz[c + w];
                float ph = (w ? vh.y : vh.x) + bh[c + w];
                float z = 1.0f / (1.0f + expf(-pz));
                float h = tanhf(ph);
                float st = state[(size_t)row * UN + c + w];
                out[(size_t)row * UN + c + w] = st + z * (h - st);
            }
        }
    }
}

// =====================================================================
extern "C" void kernel_launch(void* const* d_in, const int* in_sizes, int n_in,
                              void* d_out, int out_size)
{
    const float* inputs = (const float*)d_in[0];
    const float* state  = (const float*)d_in[1];
    const float* adj    = (const float*)d_in[2];
    const float* wa     = (const float*)d_in[3];
    const float* wgcn   = (const float*)d_in[4];
    const float* wz     = (const float*)d_in[5];
    const float* uz     = (const float*)d_in[6];
    const float* bz     = (const float*)d_in[7];
    const float* wh     = (const float*)d_in[8];
    const float* uh     = (const float*)d_in[9];
    const float* bh     = (const float*)d_in[10];
    float* out = (float*)d_out;

    cudaFuncSetAttribute(kernelA, cudaFuncAttributeMaxDynamicSharedMemorySize, SMEMSZ);
    cudaFuncSetAttribute(kernelB, cudaFuncAttributeMaxDynamicSharedMemorySize, SMEMSZ);

    kPrepW<<<dim3(NN/32, UN/32), 256>>>(wgcn);
    kPrepIn<<<(BT*NN/4)/256, 256>>>(inputs);
    kernelA<<<dim3(32, 2, 2), 256, SMEMSZ>>>(adj, wa);
    kReduceGT<<<dim3(NN/32, UN/32), 256>>>();
    kernelB<<<dim3(4, 2, 16), 256, SMEMSZ>>>();
    kReduceX<<<128, 256>>>();
    kernelC<<<dim3(16, 8), 128>>>(state, wz, uz, bz, wh, uh, bh, out);
}

// round 5
// speedup vs baseline: 3.4050x; 1.1793x over previous
#include <cuda_runtime.h>
#include <math.h>
#include <stdint.h>

typedef unsigned long long ull;
typedef unsigned short u16;

#define NN 4096
#define UN 256
#define BT 512

// ================= helpers =================
__device__ __forceinline__ ull pack2(float x, float y){
    ull r; asm("mov.b64 %0, {%1, %2};" : "=l"(r) : "f"(x), "f"(y)); return r;
}
__device__ __forceinline__ void fma2(ull& d, ull a, ull b){
    asm("fma.rn.f32x2 %0, %1, %2, %3;" : "=l"(d) : "l"(a), "l"(b), "l"(d));
}
__device__ __forceinline__ float2 unpack2(ull v){
    float lo, hi; asm("mov.b64 {%0, %1}, %2;" : "=f"(lo), "=f"(hi) : "l"(v));
    return make_float2(lo, hi);
}
__device__ __forceinline__ uint32_t smem_u32(const void* p){
    uint32_t a;
    asm("{ .reg .u64 t; cvta.to.shared.u64 t, %1; cvt.u32.u64 %0, t; }" : "=r"(a) : "l"(p));
    return a;
}
__device__ __forceinline__ void cpasync16(uint32_t daddr, const void* gptr){
    asm volatile("cp.async.cg.shared.global [%0], [%1], 16;" :: "r"(daddr), "l"(gptr));
}
#define CP_COMMIT asm volatile("cp.async.commit_group;" ::: "memory")
#define CP_WAIT0  asm volatile("cp.async.wait_group 0;" ::: "memory")

// fp16 hi/lo split of a pair of floats -> packed f16x2 words (low k in low 16 bits)
__device__ __forceinline__ void split2h(float v0, float v1, uint32_t& hp, uint32_t& lp){
    u16 h0, h1, l0, l1;
    asm("cvt.rn.f16.f32 %0, %1;" : "=h"(h0) : "f"(v0));
    asm("cvt.rn.f16.f32 %0, %1;" : "=h"(h1) : "f"(v1));
    float f0, f1;
    asm("cvt.f32.f16 %0, %1;" : "=f"(f0) : "h"(h0));
    asm("cvt.f32.f16 %0, %1;" : "=f"(f1) : "h"(h1));
    asm("cvt.rn.f16.f32 %0, %1;" : "=h"(l0) : "f"(v0 - f0));
    asm("cvt.rn.f16.f32 %0, %1;" : "=h"(l1) : "f"(v1 - f1));
    asm("mov.b32 %0, {%1, %2};" : "=r"(hp) : "h"(h0), "h"(h1));
    asm("mov.b32 %0, {%1, %2};" : "=r"(lp) : "h"(l0), "h"(l1));
}
__device__ __forceinline__ void split1h(float v, u16& h, u16& l){
    u16 hb, lb;
    asm("cvt.rn.f16.f32 %0, %1;" : "=h"(hb) : "f"(v));
    float hf;
    asm("cvt.f32.f16 %0, %1;" : "=f"(hf) : "h"(hb));
    asm("cvt.rn.f16.f32 %0, %1;" : "=h"(lb) : "f"(v - hf));
    h = hb; l = lb;
}
__device__ __forceinline__ u16 cvt1h(float v){
    u16 hb;
    asm("cvt.rn.f16.f32 %0, %1;" : "=h"(hb) : "f"(v));
    return hb;
}

__device__ __forceinline__ void mma16816h(float* d, const uint32_t* a, const uint32_t* b){
    asm volatile("mma.sync.aligned.m16n8k16.row.col.f32.f16.f16.f32 "
        "{%0,%1,%2,%3}, {%4,%5,%6,%7}, {%8,%9}, {%0,%1,%2,%3};"
        : "+f"(d[0]), "+f"(d[1]), "+f"(d[2]), "+f"(d[3])
        : "r"(a[0]), "r"(a[1]), "r"(a[2]), "r"(a[3]), "r"(b[0]), "r"(b[1]));
}

// ================= static device scratch =================
__device__ __align__(16) float g_partialG[2u * NN * UN];   // 8 MB
__device__ __align__(16) u16   g_wth[UN * NN];             // 2 MB  w_gcn^T fp16 (single plane)
__device__ __align__(16) u16   g_Gt_hi[UN * NN];           // 2 MB  G^T fp16 hi [256][4096]
__device__ __align__(16) u16   g_Gt_lo[UN * NN];           // 2 MB
__device__ __align__(16) u16   g_inb_hi[BT * NN];          // 4 MB  inputs fp16 hi
__device__ __align__(16) u16   g_inb_lo[BT * NN];          // 4 MB
__device__ __align__(16) float g_partialX[16u * BT * UN];  // 8 MB
__device__ __align__(16) float g_X[BT * UN];               // 0.5 MB

// ================= SMEM tile geometry =================
// row stride 80 bytes (32 halves data + pad): conflict-free frag LDS, 16B aligned
#define ROWB 80
// kernelA layout: [A_hi 10240][A_lo 10240][B 10240]
#define A_OFF_AHI 0
#define A_OFF_ALO 10240
#define A_OFF_B   20480
#define A_BUFST   30720
#define A_SMEMSZ  (2 * A_BUFST)
// kernelB layout: [A_hi][A_lo][B_hi][B_lo]
#define B_OFF_AHI 0
#define B_OFF_ALO 10240
#define B_OFF_BHI 20480
#define B_OFF_BLO 30720
#define B_BUFST   40960
#define B_SMEMSZ  (2 * B_BUFST)

// -------- 2-term mma stage (kernelA): A hi/lo, B single --------
__device__ __forceinline__ void mma_stage2(const char* buf, float (&acc)[4][4][4],
                                           int wid, int g, int tig){
    const int am = (wid & 1) * 64 + g;
    const int bn = (wid >> 1) * 32 + g;
#pragma unroll
    for (int s = 0; s < 2; s++){
        const int ko = s * 32 + tig * 4;
        uint32_t bh[4][2];
#pragma unroll
        for (int ni = 0; ni < 4; ni++){
            const char* p = buf + A_OFF_B + (bn + ni*8) * ROWB + ko;
            bh[ni][0] = *(const uint32_t*)p;
            bh[ni][1] = *(const uint32_t*)(p + 16);
        }
#pragma unroll
        for (int mi = 0; mi < 4; mi++){
            const char* p = buf + A_OFF_AHI + (am + mi*16) * ROWB + ko;
            uint32_t ah[4] = { *(const uint32_t*)p,        *(const uint32_t*)(p + 8*ROWB),
                               *(const uint32_t*)(p + 16), *(const uint32_t*)(p + 8*ROWB + 16) };
            const char* q = buf + A_OFF_ALO + (am + mi*16) * ROWB + ko;
            uint32_t al[4] = { *(const uint32_t*)q,        *(const uint32_t*)(q + 8*ROWB),
                               *(const uint32_t*)(q + 16), *(const uint32_t*)(q + 8*ROWB + 16) };
#pragma unroll
            for (int ni = 0; ni < 4; ni++){
                mma16816h(acc[mi][ni], ah, bh[ni]);
                mma16816h(acc[mi][ni], al, bh[ni]);
            }
        }
    }
}

// -------- 3-term mma stage (kernelB): A hi/lo, B hi/lo, drop lo*lo --------
__device__ __forceinline__ void mma_stage3(const char* buf, float (&acc)[4][4][4],
                                           int wid, int g, int tig){
    const int am = (wid & 1) * 64 + g;
    const int bn = (wid >> 1) * 32 + g;
#pragma unroll
    for (int s = 0; s < 2; s++){
        const int ko = s * 32 + tig * 4;
        uint32_t bh[4][2], bl[4][2];
#pragma unroll
        for (int ni = 0; ni < 4; ni++){
            const char* p = buf + B_OFF_BHI + (bn + ni*8) * ROWB + ko;
            bh[ni][0] = *(const uint32_t*)p;
            bh[ni][1] = *(const uint32_t*)(p + 16);
            const char* q = buf + B_OFF_BLO + (bn + ni*8) * ROWB + ko;
            bl[ni][0] = *(const uint32_t*)q;
            bl[ni][1] = *(const uint32_t*)(q + 16);
        }
#pragma unroll
        for (int mi = 0; mi < 4; mi++){
            const char* p = buf + B_OFF_AHI + (am + mi*16) * ROWB + ko;
            uint32_t ah[4] = { *(const uint32_t*)p,        *(const uint32_t*)(p + 8*ROWB),
                               *(const uint32_t*)(p + 16), *(const uint32_t*)(p + 8*ROWB + 16) };
            const char* q = buf + B_OFF_ALO + (am + mi*16) * ROWB + ko;
            uint32_t al[4] = { *(const uint32_t*)q,        *(const uint32_t*)(q + 8*ROWB),
                               *(const uint32_t*)(q + 16), *(const uint32_t*)(q + 8*ROWB + 16) };
#pragma unroll
            for (int ni = 0; ni < 4; ni++){
                mma16816h(acc[mi][ni], ah, bh[ni]);
                mma16816h(acc[mi][ni], ah, bl[ni]);
                mma16816h(acc[mi][ni], al, bh[ni]);
            }
        }
    }
}

// =====================================================================
// kPrepW: w_gcn [4096][256] -> g_wth [256][4096] fp16 (transpose)
// =====================================================================
__global__ void kPrepW(const float* __restrict__ wgcn)
{
    __shared__ float tile[32][33];
    const int k0 = blockIdx.x * 32, n0 = blockIdx.y * 32;
    const int c = threadIdx.x & 31, r = threadIdx.x >> 5;
#pragma unroll
    for (int i = 0; i < 4; i++)
        tile[r + 8*i][c] = wgcn[(size_t)(k0 + r + 8*i) * UN + n0 + c];
    __syncthreads();
#pragma unroll
    for (int i = 0; i < 4; i++){
        size_t o = (size_t)(n0 + r + 8*i) * NN + k0 + c;
        g_wth[o] = cvt1h(tile[c][r + 8*i]);
    }
}

// =====================================================================
// kPrepIn: inputs fp32 -> fp16 hi/lo
// =====================================================================
__global__ void kPrepIn(const float* __restrict__ inputs)
{
    int i = blockIdx.x * blockDim.x + threadIdx.x;    // 524288 float4s
    float4 v = ((const float4*)inputs)[i];
    uint32_t h0, l0, h1, l1;
    split2h(v.x, v.y, h0, l0);
    split2h(v.z, v.w, h1, l1);
    ((uint2*)g_inb_hi)[i] = make_uint2(h0, h1);
    ((uint2*)g_inb_lo)[i] = make_uint2(l0, l1);
}

// =====================================================================
// kernelA: partialG[ks] = adj_mix[:, ks*2048:+2048] @ w_gcn, fp16 2-term
// grid (32 m, 2 n, 2 ksplit), 256 threads
// =====================================================================
#define KA_NST 64     // 2048 / 32

__global__ __launch_bounds__(256, 1) void kernelA(const float* __restrict__ adj,
                                                  const float* __restrict__ wap)
{
    extern __shared__ __align__(16) char smem[];
    const uint32_t sb = smem_u32(smem);
    const int tid = threadIdx.x, wid = tid >> 5, lane = tid & 31;
    const int g = lane >> 2, tig = lane & 3;
    const int m0 = blockIdx.x * 128, n0 = blockIdx.y * 128;
    const int kbase = blockIdx.z * 2048;
    const float w0 = wap[0], w1 = wap[1], w2 = wap[2];
    const size_t GS = (size_t)NN * NN;

    float acc[4][4][4];
#pragma unroll
    for (int a = 0; a < 4; a++)
#pragma unroll
        for (int b = 0; b < 4; b++)
#pragma unroll
            for (int c = 0; c < 4; c++) acc[a][b][c] = 0.f;

    float4 ra[4][3];

    auto issueB = [&](int t, int b){
#pragma unroll
        for (int j = 0; j < 2; j++){
            int f = j*256 + tid, row = f >> 2, c = f & 3;
            uint32_t daddr = sb + b*A_BUFST + A_OFF_B + row*ROWB + c*16;
            size_t go = (size_t)(n0 + row) * NN + kbase + t*32 + c*8;
            cpasync16(daddr, g_wth + go);
        }
        CP_COMMIT;
    };
    auto loadA = [&](int t){
#pragma unroll
        for (int j = 0; j < 4; j++){
            int f = j*256 + tid, row = f >> 3, q = f & 7;
            const float* p = adj + (size_t)(m0 + row) * NN + kbase + t*32 + q*4;
            ra[j][0] = __ldg((const float4*)p);
            ra[j][1] = __ldg((const float4*)(p + GS));
            ra[j][2] = __ldg((const float4*)(p + 2*GS));
        }
    };
    auto storeA = [&](int b){
        char* base = smem + b*A_BUFST;
#pragma unroll
        for (int j = 0; j < 4; j++){
            int f = j*256 + tid, row = f >> 3, q = f & 7;
            float vx = fmaf(w0, ra[j][0].x, fmaf(w1, ra[j][1].x, w2*ra[j][2].x));
            float vy = fmaf(w0, ra[j][0].y, fmaf(w1, ra[j][1].y, w2*ra[j][2].y));
            float vz = fmaf(w0, ra[j][0].z, fmaf(w1, ra[j][1].z, w2*ra[j][2].z));
            float vw = fmaf(w0, ra[j][0].w, fmaf(w1, ra[j][1].w, w2*ra[j][2].w));
            uint32_t h0, l0, h1, l1;
            split2h(vx, vy, h0, l0);
            split2h(vz, vw, h1, l1);
            *(uint2*)(base + A_OFF_AHI + row*ROWB + q*8) = make_uint2(h0, h1);
            *(uint2*)(base + A_OFF_ALO + row*ROWB + q*8) = make_uint2(l0, l1);
        }
    };

    issueB(0, 0);
    loadA(0); storeA(0);
    CP_WAIT0; __syncthreads();

    for (int t = 0; t < KA_NST; t++){
        const int b = t & 1;
        if (t + 1 < KA_NST){ issueB(t + 1, b ^ 1); loadA(t + 1); }
        mma_stage2(smem + b*A_BUFST, acc, wid, g, tig);
        if (t + 1 < KA_NST) storeA(b ^ 1);
        CP_WAIT0; __syncthreads();
    }

    float* dst = g_partialG + (size_t)blockIdx.z * (NN * UN);
#pragma unroll
    for (int mi = 0; mi < 4; mi++){
#pragma unroll
        for (int ni = 0; ni < 4; ni++){
            int m = m0 + (wid & 1)*64 + mi*16 + g;
            int n = n0 + (wid >> 1)*32 + ni*8 + tig*2;
            *(float2*)(dst + (size_t)m * UN + n)       = make_float2(acc[mi][ni][0], acc[mi][ni][1]);
            *(float2*)(dst + (size_t)(m + 8) * UN + n) = make_float2(acc[mi][ni][2], acc[mi][ni][3]);
        }
    }
}

// =====================================================================
// kReduceGT: G = sum of 2 partials; transpose + fp16 split -> g_Gt_hi/lo
// =====================================================================
__global__ void kReduceGT()
{
    __shared__ float tile[32][33];
    const int k0 = blockIdx.x * 32, n0 = blockIdx.y * 32;
    const int c = threadIdx.x & 31, r = threadIdx.x >> 5;
#pragma unroll
    for (int i = 0; i < 4; i++){
        size_t o = (size_t)(k0 + r + 8*i) * UN + n0 + c;
        tile[r + 8*i][c] = g_partialG[o] + g_partialG[(size_t)NN*UN + o];
    }
    __syncthreads();
#pragma unroll
    for (int i = 0; i < 4; i++){
        float v = tile[c][r + 8*i];
        size_t o = (size_t)(n0 + r + 8*i) * NN + k0 + c;
        split1h(v, g_Gt_hi[o], g_Gt_lo[o]);
    }
}

// =====================================================================
// kernelB: partialX[ks] = inputs[:, kchunk] @ G[kchunk, :], fp16 3-term
// grid (4 m, 2 n, 16 ksplit), kchunk 256, NST 8
// =====================================================================
#define KB_NST 8

__global__ __launch_bounds__(256, 1) void kernelB()
{
    extern __shared__ __align__(16) char smem[];
    const uint32_t sb = smem_u32(smem);
    const int tid = threadIdx.x, wid = tid >> 5, lane = tid & 31;
    const int g = lane >> 2, tig = lane & 3;
    const int m0 = blockIdx.x * 128, n0 = blockIdx.y * 128;
    const int kbase = blockIdx.z * 256;

    float acc[4][4][4];
#pragma unroll
    for (int a = 0; a < 4; a++)
#pragma unroll
        for (int b = 0; b < 4; b++)
#pragma unroll
            for (int c = 0; c < 4; c++) acc[a][b][c] = 0.f;

    auto issue = [&](int t, int b){
#pragma unroll
        for (int j = 0; j < 2; j++){
            int f = j*256 + tid, row = f >> 2, c = f & 3;
            uint32_t daddr = sb + b*B_BUFST + row*ROWB + c*16;
            size_t ga = (size_t)(m0 + row) * NN + kbase + t*32 + c*8;
            size_t gb = (size_t)(n0 + row) * NN + kbase + t*32 + c*8;
            cpasync16(daddr + B_OFF_AHI, g_inb_hi + ga);
            cpasync16(daddr + B_OFF_ALO, g_inb_lo + ga);
            cpasync16(daddr + B_OFF_BHI, g_Gt_hi + gb);
            cpasync16(daddr + B_OFF_BLO, g_Gt_lo + gb);
        }
        CP_COMMIT;
    };

    issue(0, 0);
    CP_WAIT0; __syncthreads();

    for (int t = 0; t < KB_NST; t++){
        const int b = t & 1;
        if (t + 1 < KB_NST) issue(t + 1, b ^ 1);
        mma_stage3(smem + b*B_BUFST, acc, wid, g, tig);
        CP_WAIT0; __syncthreads();
    }

    float* dst = g_partialX + (size_t)blockIdx.z * (BT * UN);
#pragma unroll
    for (int mi = 0; mi < 4; mi++){
#pragma unroll
        for (int ni = 0; ni < 4; ni++){
            int m = m0 + (wid & 1)*64 + mi*16 + g;
            int n = n0 + (wid >> 1)*32 + ni*8 + tig*2;
            *(float2*)(dst + (size_t)m * UN + n)       = make_float2(acc[mi][ni][0], acc[mi][ni][1]);
            *(float2*)(dst + (size_t)(m + 8) * UN + n) = make_float2(acc[mi][ni][2], acc[mi][ni][3]);
        }
    }
}

// =====================================================================
// kReduceX: X = relu(sum of 16 partials)
// =====================================================================
__global__ void kReduceX()
{
    int i = blockIdx.x * blockDim.x + threadIdx.x;   // 32768 float4s
    const float4* p = (const float4*)g_partialX;
    float4 s = p[i];
#pragma unroll
    for (int s16 = 1; s16 < 16; s16++){
        float4 t = p[(size_t)s16 * (BT*UN/4) + i];
        s.x += t.x; s.y += t.y; s.z += t.z; s.w += t.w;
    }
    s.x = fmaxf(s.x, 0.f); s.y = fmaxf(s.y, 0.f);
    s.z = fmaxf(s.z, 0.f); s.w = fmaxf(s.w, 0.f);
    ((float4*)g_X)[i] = s;
}

// =====================================================================
// kernelC: GRU gates (fp32 CUDA cores)
// =====================================================================
__global__ __launch_bounds__(128, 4) void kernelC(const float* __restrict__ state,
    const float* __restrict__ wz, const float* __restrict__ uz, const float* __restrict__ bz,
    const float* __restrict__ wh, const float* __restrict__ uh, const float* __restrict__ bh,
    float* __restrict__ out)
{
    __shared__ float Xs[32][33];
    __shared__ float Ss[32][33];
    __shared__ float Wz[32][32], Uz[32][32], Wh[32][32], Uh[32][32];

    const int tid = threadIdx.x;
    const int tx = tid & 7;
    const int ty = tid >> 3;
    const int m0 = blockIdx.x * 32;
    const int n0 = blockIdx.y * 32;

    ull accz[2][2], acch[2][2];
#pragma unroll
    for (int i = 0; i < 2; i++)
#pragma unroll
        for (int j = 0; j < 2; j++){ accz[i][j] = 0ULL; acch[i][j] = 0ULL; }

    for (int kt = 0; kt < UN / 32; kt++){
        const int k0 = kt * 32;
        float4 xv[2], sv[2], wzv[2], uzv[2], whv[2], uhv[2];
#pragma unroll
        for (int u = 0; u < 2; u++){
            int f = tid + 128*u;
            int row = f >> 3; int c4 = (f & 7) * 4;
            xv[u]  = *(const float4*)(g_X  + (size_t)(m0 + row) * UN + k0 + c4);
            sv[u]  = *(const float4*)(state + (size_t)(m0 + row) * UN + k0 + c4);
            wzv[u] = *(const float4*)(wz + (size_t)(k0 + row) * UN + n0 + c4);
            uzv[u] = *(const float4*)(uz + (size_t)(k0 + row) * UN + n0 + c4);
            whv[u] = *(const float4*)(wh + (size_t)(k0 + row) * UN + n0 + c4);
            uhv[u] = *(const float4*)(uh + (size_t)(k0 + row) * UN + n0 + c4);
        }
        __syncthreads();
#pragma unroll
        for (int u = 0; u < 2; u++){
            int f = tid + 128*u;
            int row = f >> 3; int c4 = (f & 7) * 4;
            Xs[c4+0][row] = xv[u].x; Xs[c4+1][row] = xv[u].y;
            Xs[c4+2][row] = xv[u].z; Xs[c4+3][row] = xv[u].w;
            Ss[c4+0][row] = sv[u].x; Ss[c4+1][row] = sv[u].y;
            Ss[c4+2][row] = sv[u].z; Ss[c4+3][row] = sv[u].w;
            *(float4*)&Wz[row][c4] = wzv[u];
            *(float4*)&Uz[row][c4] = uzv[u];
            *(float4*)&Wh[row][c4] = whv[u];
            *(float4*)&Uh[row][c4] = uhv[u];
        }
        __syncthreads();

#pragma unroll 8
        for (int kk = 0; kk < 32; kk++){
            float x0 = Xs[kk][ty*2], x1 = Xs[kk][ty*2+1];
            float s0 = Ss[kk][ty*2], s1 = Ss[kk][ty*2+1];
            ull xx0 = pack2(x0, x0), xx1 = pack2(x1, x1);
            ull ss0 = pack2(s0, s0), ss1 = pack2(s1, s1);
            const ull* wzp = (const ull*)&Wz[kk][tx*4];
            const ull* uzp = (const ull*)&Uz[kk][tx*4];
            const ull* whp = (const ull*)&Wh[kk][tx*4];
            const ull* uhp = (const ull*)&Uh[kk][tx*4];
            ull wz0 = wzp[0], wz1 = wzp[1], uz0 = uzp[0], uz1 = uzp[1];
            ull wh0 = whp[0], wh1 = whp[1], uh0 = uhp[0], uh1 = uhp[1];
            fma2(accz[0][0], xx0, wz0); fma2(accz[0][1], xx0, wz1);
            fma2(accz[1][0], xx1, wz0); fma2(accz[1][1], xx1, wz1);
            fma2(accz[0][0], ss0, uz0); fma2(accz[0][1], ss0, uz1);
            fma2(accz[1][0], ss1, uz0); fma2(accz[1][1], ss1, uz1);
            fma2(acch[0][0], xx0, wh0); fma2(acch[0][1], xx0, wh1);
            fma2(acch[1][0], xx1, wh0); fma2(acch[1][1], xx1, wh1);
            fma2(acch[0][0], ss0, uh0); fma2(acch[0][1], ss0, uh1);
            fma2(acch[1][0], ss1, uh0); fma2(acch[1][1], ss1, uh1);
        }
    }

#pragma unroll
    for (int i = 0; i < 2; i++){
        int row = m0 + ty*2 + i;
#pragma unroll
        for (int jp = 0; jp < 2; jp++){
            float2 vz = unpack2(accz[i][jp]);
            float2 vh = unpack2(acch[i][jp]);
            int c = n0 + tx*4 + jp*2;
#pragma unroll
            for (int w = 0; w < 2; w++){
                float pz = (w ? vz.y : vz.x) + bz[c + w];
                float ph = (w ? vh.y : vh.x) + bh[c + w];
                float z = 1.0f / (1.0f + expf(-pz));
                float h = tanhf(ph);
                float st = state[(size_t)row * UN + c + w];
                out[(size_t)row * UN + c + w] = st + z * (h - st);
            }
        }
    }
}

// =====================================================================
extern "C" void kernel_launch(void* const* d_in, const int* in_sizes, int n_in,
                              void* d_out, int out_size)
{
    const float* inputs = (const float*)d_in[0];
    const float* state  = (const float*)d_in[1];
    const float* adj    = (const float*)d_in[2];
    const float* wa     = (const float*)d_in[3];
    const float* wgcn   = (const float*)d_in[4];
    const float* wz     = (const float*)d_in[5];
    const float* uz     = (const float*)d_in[6];
    const float* bz     = (const float*)d_in[7];
    const float* wh     = (const float*)d_in[8];
    const float* uh     = (const float*)d_in[9];
    const float* bh     = (const float*)d_in[10];
    float* out = (float*)d_out;

    cudaFuncSetAttribute(kernelA, cudaFuncAttributeMaxDynamicSharedMemorySize, A_SMEMSZ);
    cudaFuncSetAttribute(kernelB, cudaFuncAttributeMaxDynamicSharedMemorySize, B_SMEMSZ);

    kPrepW<<<dim3(NN/32, UN/32), 256>>>(wgcn);
    kPrepIn<<<(BT*NN/4)/256, 256>>>(inputs);
    kernelA<<<dim3(32, 2, 2), 256, A_SMEMSZ>>>(adj, wa);
    kReduceGT<<<dim3(NN/32, UN/32), 256>>>();
    kernelB<<<dim3(4, 2, 16), 256, B_SMEMSZ>>>();
    kReduceX<<<128, 256>>>();
    kernelC<<<dim3(16, 8), 128>>>(state, wz, uz, bz, wh, uh, bh, out);
}